// round 13
// baseline (speedup 1.0000x reference)
#include <cuda_runtime.h>

#define B_  4
#define K_  16
#define H_  480
#define W_  640
#define HW_ (H_*W_)
#define P_  200000

// Truncation threshold. Measured linear law rel_err ~= 0.48*EPS_T:
// 1e-4 -> 4.14e-5, 5e-4 -> 2.32e-4, 1e-3 -> 4.80e-4. Predict ~7.3e-4 here.
#define EPS_T 1.5e-3f

// Pre-packed point-cloud features: one aligned 16B row per point -> one 32B
// L2 sector per gather.
__device__ float4 g_tab[P_];

__global__ void prep_kernel(const float* __restrict__ pt) {
    int i = blockIdx.x * blockDim.x + threadIdx.x;
    if (i < P_) {
        g_tab[i] = make_float4(pt[i], pt[P_ + i], pt[2 * P_ + i], 0.f);
    }
}

// Converged shape (R12): 128-thread blocks, 16/SM, regs pinned to 32.
__global__ void __launch_bounds__(128, 16) composite_kernel(
    const int*   __restrict__ frag,   // int32 (JAX demotes int64 without x64 mode)
    const float* __restrict__ alpha,
    const float* __restrict__ im,
    float*       __restrict__ out)
{
    int p = blockIdx.x * blockDim.x + threadIdx.x;  // pixel within a batch image
    int b = blockIdx.y;
    size_t base = (size_t)b * K_ * HW_ + p;

    float T  = 1.f;
    float c0 = 0.f, c1 = 0.f, c2 = 0.f;
    bool  bg = false;

    #pragma unroll
    for (int half = 0; half < 2; half++) {
        // Batch-load 8 frags + 8 alphas (16 independent LDGs -> full MLP).
        int   f[8];
        float w[8];
        #pragma unroll
        for (int j = 0; j < 8; j++) {
            size_t off = base + (size_t)(half * 8 + j) * HW_;
            f[j] = frag[off];
            w[j] = alpha[off];
        }
        if (half == 0) {
            bg = (f[0] < 0);
            if (bg) T = 0.f;   // background: zero every weight -> zero gathers
        }

        // Weight chain in pure FMA; data-predicated truncation.
        #pragma unroll
        for (int j = 0; j < 8; j++) {
            float av = (f[j] >= 0) ? w[j] : 0.f;
            w[j] = (T > EPS_T) ? av * T : 0.f;   // exclusive-transmittance weight
            T *= (1.f - av);
        }

        // Predicated independent gathers (skip all zero-weight layers).
        #pragma unroll
        for (int j = 0; j < 8; j++) {
            if (w[j] != 0.f) {
                float4 ft = __ldg(&g_tab[f[j]]);
                c0 = fmaf(w[j], ft.x, c0);
                c1 = fmaf(w[j], ft.y, c1);
                c2 = fmaf(w[j], ft.z, c2);
            }
        }
    }

    size_t ob = (size_t)b * 3 * HW_ + p;
    out[ob          ] = bg ? im[p          ] : c0;
    out[ob +     HW_] = bg ? im[p +     HW_] : c1;
    out[ob + 2 * HW_] = bg ? im[p + 2 * HW_] : c2;
}

extern "C" void kernel_launch(void* const* d_in, const int* in_sizes, int n_in,
                              void* d_out, int out_size) {
    const int*   frag  = (const int*)  d_in[0];
    const float* alpha = (const float*)d_in[1];
    const float* pt    = (const float*)d_in[2];
    const float* im    = (const float*)d_in[3];
    float*       out   = (float*)      d_out;

    prep_kernel<<<(P_ + 255) / 256, 256>>>(pt);

    dim3 grid(HW_ / 128, B_);   // 2400 x 4 blocks, 128 pixels per block
    composite_kernel<<<grid, 128>>>(frag, alpha, im, out);
}

// round 14
// speedup vs baseline: 1.0056x; 1.0056x over previous
#include <cuda_runtime.h>

#define B_  4
#define K_  16
#define H_  480
#define W_  640
#define HW_ (H_*W_)
#define P_  200000

// Truncation threshold. Measured (R7/R8/R10/R12): rel_err = 4.80e-4 (gate 1e-3).
// 1.5e-3 (R13) bought zero time for 1.5x the error -> reverted.
#define EPS_T 1e-3f

// Pre-packed point-cloud features: one aligned 16B row per point -> one 32B
// L2 sector per gather.
__device__ float4 g_tab[P_];

__global__ void prep_kernel(const float* __restrict__ pt) {
    int i = blockIdx.x * blockDim.x + threadIdx.x;
    if (i < P_) {
        g_tab[i] = make_float4(pt[i], pt[P_ + i], pt[2 * P_ + i], 0.f);
    }
}

// Converged shape (R12): 128-thread blocks, 16/SM, regs pinned to 32.
// Epilogue made explicitly branchy so the im[] loads are issued ONLY for
// background lanes (25%) instead of feeding a select in every lane.
__global__ void __launch_bounds__(128, 16) composite_kernel(
    const int*   __restrict__ frag,   // int32 (JAX demotes int64 without x64 mode)
    const float* __restrict__ alpha,
    const float* __restrict__ im,
    float*       __restrict__ out)
{
    int p = blockIdx.x * blockDim.x + threadIdx.x;  // pixel within a batch image
    int b = blockIdx.y;
    size_t base = (size_t)b * K_ * HW_ + p;

    float T  = 1.f;
    float c0 = 0.f, c1 = 0.f, c2 = 0.f;
    bool  bg = false;

    #pragma unroll
    for (int half = 0; half < 2; half++) {
        // Batch-load 8 frags + 8 alphas (16 independent LDGs -> full MLP).
        int   f[8];
        float w[8];
        #pragma unroll
        for (int j = 0; j < 8; j++) {
            size_t off = base + (size_t)(half * 8 + j) * HW_;
            f[j] = frag[off];
            w[j] = alpha[off];
        }
        if (half == 0) {
            bg = (f[0] < 0);
            if (bg) T = 0.f;   // background: zero every weight -> zero gathers
        }

        // Weight chain in pure FMA; data-predicated truncation.
        #pragma unroll
        for (int j = 0; j < 8; j++) {
            float av = (f[j] >= 0) ? w[j] : 0.f;
            w[j] = (T > EPS_T) ? av * T : 0.f;   // exclusive-transmittance weight
            T *= (1.f - av);
        }

        // Predicated independent gathers (skip all zero-weight layers).
        #pragma unroll
        for (int j = 0; j < 8; j++) {
            if (w[j] != 0.f) {
                float4 ft = __ldg(&g_tab[f[j]]);
                c0 = fmaf(w[j], ft.x, c0);
                c1 = fmaf(w[j], ft.y, c1);
                c2 = fmaf(w[j], ft.z, c2);
            }
        }
    }

    size_t ob = (size_t)b * 3 * HW_ + p;
    if (bg) {
        out[ob          ] = im[p          ];
        out[ob +     HW_] = im[p +     HW_];
        out[ob + 2 * HW_] = im[p + 2 * HW_];
    } else {
        out[ob          ] = c0;
        out[ob +     HW_] = c1;
        out[ob + 2 * HW_] = c2;
    }
}

extern "C" void kernel_launch(void* const* d_in, const int* in_sizes, int n_in,
                              void* d_out, int out_size) {
    const int*   frag  = (const int*)  d_in[0];
    const float* alpha = (const float*)d_in[1];
    const float* pt    = (const float*)d_in[2];
    const float* im    = (const float*)d_in[3];
    float*       out   = (float*)      d_out;

    prep_kernel<<<(P_ + 255) / 256, 256>>>(pt);

    dim3 grid(HW_ / 128, B_);   // 2400 x 4 blocks, 128 pixels per block
    composite_kernel<<<grid, 128>>>(frag, alpha, im, out);
}